// round 4
// baseline (speedup 1.0000x reference)
#include <cuda_runtime.h>
#include <math.h>

#define TSEQ 500
#define BATCH 512

typedef unsigned long long u64;

__device__ __forceinline__ void ffma2(u64& d, u64 a, u64 b, u64 c) {
    asm("fma.rn.f32x2 %0, %1, %2, %3;" : "=l"(d) : "l"(a), "l"(b), "l"(c));
}
__device__ __forceinline__ float2 up2(u64 v) {
    float2 f; asm("mov.b64 {%0,%1}, %2;" : "=f"(f.x), "=f"(f.y) : "l"(v)); return f;
}
__device__ __forceinline__ u64 pk2(float x, float y) {
    u64 v; asm("mov.b64 %0, {%1,%2};" : "=l"(v) : "f"(x), "f"(y)); return v;
}

// Thread layout: tid = row*4 + q ; row in [0,64), q in [0,4).
// Thread (row,q) owns P[row][16q..16q+15] as 8 packed f32x2 regs,
// and the H row strip H[row][16q..16q+15] (constant, 8 packed regs).
// mu[row] and D[row]=y[row]-h_row.mu live in q==0 registers.

__global__ void __launch_bounds__(256, 4)
akf_main(const float* __restrict__ ext, const float* __restrict__ obs,
         const float* __restrict__ mu0, const float* __restrict__ sg0,
         const float* __restrict__ lsig, const float* __restrict__ Bm,
         const float* __restrict__ Hm, const float* __restrict__ ldel,
         float* __restrict__ out)
{
    __shared__ __align__(16) float sh_H[64 * 64];
    __shared__ __align__(16) float sh_mu[64];
    __shared__ __align__(16) float vbuf[2][64];
    __shared__ float sh_y[64];
    __shared__ float sh_D[64];
    __shared__ float sh_r[64];
    __shared__ float sh_u[32];

    const int b   = blockIdx.x;
    const int tid = threadIdx.x;
    const int row = tid >> 2;
    const int q   = tid & 3;
    const int c0  = q << 4;
    const bool q0 = (q == 0);
    const bool diag_owner = ((row >> 4) == q);
    const int  dj = row & 15;

    for (int i = tid; i < 4096; i += 256) sh_H[i] = Hm[i];
    if (tid < 64) { float e = expf(ldel[tid]); sh_r[tid] = e * e; }

    // constant H row strip in registers (packed)
    u64 HR[8];
    {
        const float* hp = Hm + row * 64 + c0;
        #pragma unroll
        for (int k = 0; k < 8; ++k) HR[k] = pk2(hp[2 * k], hp[2 * k + 1]);
    }
    float qv; { float e = expf(lsig[row]); qv = e * e; }

    // P strip (packed), init diag(sigma0^2)
    u64 P2[8];
    #pragma unroll
    for (int k = 0; k < 8; ++k) P2[k] = 0ull;
    float s0 = sg0[b * 64 + row];
    if (diag_owner) {
        float2 d = up2(P2[dj >> 1]);
        if (dj & 1) d.y = s0 * s0; else d.x = s0 * s0;
        P2[dj >> 1] = pk2(d.x, d.y);
    }
    float mu = mu0[b * 64 + row];   // valid in q==0
    float Dreg = 0.0f;              // valid in q==0

    float* outmu = out;
    float* outls = out + (size_t)TSEQ * BATCH * 64;
    if (q0) outmu[b * 64 + row] = mu;
    if (diag_owner) outls[b * 64 + row] = logf(s0);
    __syncthreads();

    for (int t = 1; t < TSEQ; ++t) {
        if (tid < 64) sh_y[tid] = obs[((size_t)t * BATCH + b) * 64 + tid];
        if (tid < 32) sh_u[tid] = ext[((size_t)(t - 1) * BATCH + b) * 32 + tid];
        __syncthreads();

        // mu_pred = mu + B u ; publish to smem
        {
            const float* Br = Bm + row * 32 + (q << 3);
            float a = 0.0f;
            #pragma unroll
            for (int k = 0; k < 8; ++k) a += Br[k] * sh_u[(q << 3) + k];
            a += __shfl_xor_sync(0xffffffffu, a, 1);
            a += __shfl_xor_sync(0xffffffffu, a, 2);
            if (q0) { mu += a; sh_mu[row] = mu; }
        }
        // P += diag(q)
        if (diag_owner) {
            float2 d = up2(P2[dj >> 1]);
            if (dj & 1) d.y += qv; else d.x += qv;
            P2[dj >> 1] = pk2(d.x, d.y);
        }
        __syncthreads();

        // D = y - H mu_pred
        {
            const ulonglong2* mp = (const ulonglong2*)&sh_mu[c0];
            u64 za = 0, zb = 0;
            #pragma unroll
            for (int k = 0; k < 4; ++k) {
                ulonglong2 m = mp[k];
                ffma2(za, HR[2 * k],     m.x, za);
                ffma2(zb, HR[2 * k + 1], m.y, zb);
            }
            float2 fa = up2(za), fb = up2(zb);
            float z = (fa.x + fa.y) + (fb.x + fb.y);
            z += __shfl_xor_sync(0xffffffffu, z, 1);
            z += __shfl_xor_sync(0xffffffffu, z, 2);
            if (q0) { Dreg = sh_y[row] - z; sh_D[row] = Dreg; }
        }
        __syncthreads();

        // ---- 64 sequential scalar measurement updates ----
        #pragma unroll 1
        for (int i = 0; i < 64; ++i) {
            const int ib = i & 1;
            const ulonglong2* hp = (const ulonglong2*)&sh_H[(i << 6) + c0];

            // v[row] = P h_i : packed strip dot + nibble reduce
            u64 pa = 0, pb = 0;
            #pragma unroll
            for (int k = 0; k < 4; ++k) {
                ulonglong2 h = hp[k];
                ffma2(pa, P2[2 * k],     h.x, pa);
                ffma2(pb, P2[2 * k + 1], h.y, pb);
            }
            float2 fa = up2(pa), fb = up2(pb);
            float pp = (fa.x + fa.y) + (fb.x + fb.y);
            pp += __shfl_xor_sync(0xffffffffu, pp, 1);
            pp += __shfl_xor_sync(0xffffffffu, pp, 2);
            if (q0) vbuf[ib][row] = pp;
            __syncthreads();

            // v strip
            u64 V[8];
            {
                const ulonglong2* vp = (const ulonglong2*)&vbuf[ib][c0];
                #pragma unroll
                for (int k = 0; k < 4; ++k) {
                    ulonglong2 vv = vp[k];
                    V[2 * k] = vv.x; V[2 * k + 1] = vv.y;
                }
            }
            // s = h_i . v  (reload h strip, nibble reduce)
            u64 sa = 0, sb = 0;
            #pragma unroll
            for (int k = 0; k < 4; ++k) {
                ulonglong2 h = hp[k];
                ffma2(sa, h.x, V[2 * k],     sa);
                ffma2(sb, h.y, V[2 * k + 1], sb);
            }
            float2 ua = up2(sa), ub = up2(sb);
            float s = (ua.x + ua.y) + (ub.x + ub.y);
            s += __shfl_xor_sync(0xffffffffu, s, 1);
            s += __shfl_xor_sync(0xffffffffu, s, 2);

            float rs   = __fdividef(1.0f, s + sh_r[i]);
            float coef = sh_D[i] * rs;
            float w0   = -pp * rs;
            u64   w2   = pk2(w0, w0);

            // P -= v v^T / s  (strip)
            #pragma unroll
            for (int k = 0; k < 8; ++k) ffma2(P2[k], w2, V[k], P2[k]);

            // g = h_row . v  (register H strip, nibble reduce) -> D maintenance
            u64 g1 = 0, g2 = 0;
            #pragma unroll
            for (int k = 0; k < 4; ++k) {
                ffma2(g1, HR[2 * k],     V[2 * k],     g1);
                ffma2(g2, HR[2 * k + 1], V[2 * k + 1], g2);
            }
            float2 h1 = up2(g1), h2 = up2(g2);
            float g = (h1.x + h1.y) + (h2.x + h2.y);
            g += __shfl_xor_sync(0xffffffffu, g, 1);
            g += __shfl_xor_sync(0xffffffffu, g, 2);

            if (q0) {
                mu += coef * pp;
                if (row > i) {
                    Dreg -= coef * g;
                    if (row == i + 1) sh_D[row] = Dreg;
                }
            }
        }

        // ---- outputs ----
        if (q0)
            outmu[((size_t)t * BATCH + b) * 64 + row] = mu;
        if (diag_owner) {
            float2 d = up2(P2[dj >> 1]);
            float dv = (dj & 1) ? d.y : d.x;
            outls[((size_t)t * BATCH + b) * 64 + row] = 0.5f * logf(dv);
        }
        __syncthreads();
    }
}

extern "C" void kernel_launch(void* const* d_in, const int* in_sizes, int n_in,
                              void* d_out, int out_size) {
    const float* ext  = (const float*)d_in[0];   // (500, 512, 32)
    const float* obs  = (const float*)d_in[1];   // (500, 512, 64)
    const float* mu0  = (const float*)d_in[2];   // (512, 64)
    const float* sg0  = (const float*)d_in[3];   // (512, 64)
    const float* lsig = (const float*)d_in[4];   // (64,)
    const float* Bm   = (const float*)d_in[5];   // (64, 32)
    const float* H    = (const float*)d_in[6];   // (64, 64)
    const float* ldel = (const float*)d_in[7];   // (64,)
    float* out = (float*)d_out;

    akf_main<<<BATCH, 256>>>(ext, obs, mu0, sg0, lsig, Bm, H, ldel, out);
}

// round 5
// speedup vs baseline: 2.8140x; 2.8140x over previous
#include <cuda_runtime.h>
#include <math.h>

#define TSEQ 500
#define BATCH 512

// 128 threads: rg = tid>>3 (16 row-groups, 4 rows each), cg = tid&7 (8 col-groups, 8 cols).
// Thread (rg,cg) owns P[4rg..4rg+3][8cg..8cg+7] in 32 registers.
// All reductions are 3-round shfl butterflies over the cg bits (intra-warp).
// mu lives in smem, double-buffered per obs; v double-buffered per obs.

__global__ void __launch_bounds__(128, 4)
akf_main(const float* __restrict__ ext, const float* __restrict__ obs,
         const float* __restrict__ mu0, const float* __restrict__ sg0,
         const float* __restrict__ lsig, const float* __restrict__ Bm,
         const float* __restrict__ Hm, const float* __restrict__ ldel,
         float* __restrict__ out)
{
    __shared__ __align__(16) float sh_H[64 * 64];
    __shared__ __align__(16) float sh_B[64 * 32];
    __shared__ __align__(16) float sh_mu[2][64];
    __shared__ __align__(16) float sh_v[2][64];
    __shared__ float sh_y[64], sh_u[32], sh_r[64], sh_q[64];

    const int b   = blockIdx.x;
    const int tid = threadIdx.x;
    const int rg  = tid >> 3;
    const int cg  = tid & 7;
    const int r0  = rg << 2;
    const int c0  = cg << 3;

    for (int i = tid; i < 4096; i += 128) sh_H[i] = Hm[i];
    for (int i = tid; i < 2048; i += 128) sh_B[i] = Bm[i];
    if (tid < 64) {
        float e = expf(ldel[tid]); sh_r[tid] = e * e;
        float f = expf(lsig[tid]); sh_q[tid] = f * f;
    }

    float P[4][8];
    #pragma unroll
    for (int a = 0; a < 4; ++a)
        #pragma unroll
        for (int k = 0; k < 8; ++k) P[a][k] = 0.0f;

    float* outmu = out;
    float* outls = out + (size_t)TSEQ * BATCH * 64;

    if (tid < 64) {
        float m0  = mu0[b * 64 + tid];
        float s0v = sg0[b * 64 + tid];
        sh_mu[0][tid] = m0;
        outmu[b * 64 + tid] = m0;
        outls[b * 64 + tid] = logf(s0v);
    }
    #pragma unroll
    for (int a = 0; a < 4; ++a) {
        int d = r0 + a;
        if ((d >> 3) == cg) { float s0v = sg0[b * 64 + d]; P[a][d & 7] = s0v * s0v; }
    }
    __syncthreads();

    for (int t = 1; t < TSEQ; ++t) {
        // ---- load step inputs ----
        if (tid < 64) sh_y[tid] = obs[((size_t)t * BATCH + b) * 64 + tid];
        if (tid < 32) sh_u[tid] = ext[((size_t)(t - 1) * BATCH + b) * 32 + tid];
        __syncthreads();

        // ---- predict: mu += B u ; P += diag(q) ----
        if (tid < 64) {
            float s = sh_mu[0][tid];
            const float* Br = &sh_B[tid * 32];
            #pragma unroll 8
            for (int k = 0; k < 32; ++k) s += Br[k] * sh_u[k];
            sh_mu[0][tid] = s;
        }
        #pragma unroll
        for (int a = 0; a < 4; ++a) {
            int d = r0 + a;
            if ((d >> 3) == cg) P[a][d & 7] += sh_q[d];
        }
        __syncthreads();

        // ---- 64 sequential scalar measurement updates ----
        int par = 0;
        #pragma unroll 1
        for (int i = 0; i < 64; ++i) {
            const int pb = i & 1;

            // h_i column strip (8 floats)
            float4 ha = *(const float4*)&sh_H[(i << 6) + c0];
            float4 hb = *(const float4*)&sh_H[(i << 6) + c0 + 4];
            float h[8] = {ha.x, ha.y, ha.z, ha.w, hb.x, hb.y, hb.z, hb.w};

            // v partials over owned tile
            float vp[4];
            #pragma unroll
            for (int a = 0; a < 4; ++a) {
                float s = P[a][0] * h[0];
                #pragma unroll
                for (int k = 1; k < 8; ++k) s += P[a][k] * h[k];
                vp[a] = s;
            }
            // reduce over the 8 col-groups (intra-warp)
            #pragma unroll
            for (int m = 1; m < 8; m <<= 1) {
                #pragma unroll
                for (int a = 0; a < 4; ++a)
                    vp[a] += __shfl_xor_sync(0xffffffffu, vp[a], m);
            }
            if (cg == 0)
                *(float4*)&sh_v[pb][r0] = make_float4(vp[0], vp[1], vp[2], vp[3]);
            __syncthreads();

            // v and mu column strips
            float4 va = *(const float4*)&sh_v[pb][c0];
            float4 vb = *(const float4*)&sh_v[pb][c0 + 4];
            float vc[8] = {va.x, va.y, va.z, va.w, vb.x, vb.y, vb.z, vb.w};
            float4 ma = *(const float4*)&sh_mu[par][c0];
            float4 mb = *(const float4*)&sh_mu[par][c0 + 4];
            float mc[8] = {ma.x, ma.y, ma.z, ma.w, mb.x, mb.y, mb.z, mb.w};

            // s = h.v ; w = h.mu  (warp-local)
            float sp = 0.0f, wp = 0.0f;
            #pragma unroll
            for (int k = 0; k < 8; ++k) { sp += h[k] * vc[k]; wp += h[k] * mc[k]; }
            #pragma unroll
            for (int m = 1; m < 8; m <<= 1) {
                sp += __shfl_xor_sync(0xffffffffu, sp, m);
                wp += __shfl_xor_sync(0xffffffffu, wp, m);
            }

            float rs   = __fdividef(1.0f, sp + sh_r[i]);
            float coef = (sh_y[i] - wp) * rs;

            // P -= (v v^T) * rs  on owned tile
            #pragma unroll
            for (int a = 0; a < 4; ++a) {
                float w = vp[a] * rs;
                #pragma unroll
                for (int k = 0; k < 8; ++k) P[a][k] -= w * vc[k];
            }

            // mu update into the other buffer (rg==0 threads cover all 64 cols)
            if (rg == 0) {
                #pragma unroll
                for (int k = 0; k < 8; ++k) mc[k] += coef * vc[k];
                *(float4*)&sh_mu[par ^ 1][c0]     = make_float4(mc[0], mc[1], mc[2], mc[3]);
                *(float4*)&sh_mu[par ^ 1][c0 + 4] = make_float4(mc[4], mc[5], mc[6], mc[7]);
            }
            par ^= 1;
        }
        __syncthreads();   // final mu writes visible; also fences sh_y/sh_u reuse

        // ---- outputs (par is back to 0 after 64 flips) ----
        if (tid < 64)
            outmu[((size_t)t * BATCH + b) * 64 + tid] = sh_mu[0][tid];
        #pragma unroll
        for (int a = 0; a < 4; ++a) {
            int d = r0 + a;
            if ((d >> 3) == cg)
                outls[((size_t)t * BATCH + b) * 64 + d] = 0.5f * logf(P[a][d & 7]);
        }
    }
}

extern "C" void kernel_launch(void* const* d_in, const int* in_sizes, int n_in,
                              void* d_out, int out_size) {
    const float* ext  = (const float*)d_in[0];   // (500, 512, 32)
    const float* obs  = (const float*)d_in[1];   // (500, 512, 64)
    const float* mu0  = (const float*)d_in[2];   // (512, 64)
    const float* sg0  = (const float*)d_in[3];   // (512, 64)
    const float* lsig = (const float*)d_in[4];   // (64,)
    const float* Bm   = (const float*)d_in[5];   // (64, 32)
    const float* H    = (const float*)d_in[6];   // (64, 64)
    const float* ldel = (const float*)d_in[7];   // (64,)
    float* out = (float*)d_out;

    akf_main<<<BATCH, 128>>>(ext, obs, mu0, sg0, lsig, Bm, H, ldel, out);
}

// round 6
// speedup vs baseline: 3.0697x; 1.0909x over previous
#include <cuda_runtime.h>
#include <math.h>

#define TSEQ 500
#define BATCH 512

typedef unsigned long long u64;

__device__ __forceinline__ void ffma2(u64& d, u64 a, u64 b, u64 c) {
    asm("fma.rn.f32x2 %0, %1, %2, %3;" : "=l"(d) : "l"(a), "l"(b), "l"(c));
}
__device__ __forceinline__ float2 up2(u64 v) {
    float2 f; asm("mov.b64 {%0,%1}, %2;" : "=f"(f.x), "=f"(f.y) : "l"(v)); return f;
}
__device__ __forceinline__ u64 pk2(float x, float y) {
    u64 v; asm("mov.b64 %0, {%1,%2};" : "=l"(v) : "f"(x), "f"(y)); return v;
}

// 128 threads: rg = tid>>3 (16 row-groups x 4 rows), cg = tid&7 (8 col-groups x 8 cols).
// Thread (rg,cg) owns P[4rg..4rg+3][8cg..8cg+7] as 16 packed f32x2 registers.
// v reduction: 4-shuffle reduce-scatter within each 8-lane octet, scalar STS,
// recovery via LDS.128 after the (mandatory) per-obs barrier.
// mu: maintained in warp-0 registers (packed col strip, replicated across rg 0..3).

__global__ void __launch_bounds__(128, 4)
akf_main(const float* __restrict__ ext, const float* __restrict__ obs,
         const float* __restrict__ mu0, const float* __restrict__ sg0,
         const float* __restrict__ lsig, const float* __restrict__ Bm,
         const float* __restrict__ Hm, const float* __restrict__ ldel,
         float* __restrict__ out)
{
    __shared__ __align__(16) float sh_H[4096];
    __shared__ __align__(16) float sh_B[2048];
    __shared__ __align__(16) float sh_mu[64];
    __shared__ __align__(16) float sh_v[2][64];
    __shared__ float sh_y[64], sh_u[32], sh_r[64], sh_q[64];

    const int b   = blockIdx.x;
    const int tid = threadIdx.x;
    const int rg  = tid >> 3;
    const int cg  = tid & 7;
    const int r0  = rg << 2;
    const int c0  = cg << 3;
    const bool w0 = (tid < 32);

    for (int i = tid; i < 4096; i += 128) sh_H[i] = Hm[i];
    for (int i = tid; i < 2048; i += 128) sh_B[i] = Bm[i];
    if (tid < 64) {
        float e = expf(ldel[tid]); sh_r[tid] = e * e;
        float f = expf(lsig[tid]); sh_q[tid] = f * f;
    }

    u64 P2[4][4];
    #pragma unroll
    for (int a = 0; a < 4; ++a)
        #pragma unroll
        for (int k = 0; k < 4; ++k) P2[a][k] = 0ull;

    float* outmu = out;
    float* outls = out + (size_t)TSEQ * BATCH * 64;

    if (tid < 64) {
        float m0  = mu0[b * 64 + tid];
        float s0v = sg0[b * 64 + tid];
        sh_mu[tid] = m0;
        outmu[b * 64 + tid] = m0;
        outls[b * 64 + tid] = logf(s0v);
    }
    #pragma unroll
    for (int a = 0; a < 4; ++a) {
        int d = r0 + a;
        if ((d >> 3) == cg) {
            float s0v = sg0[b * 64 + d];
            int kk = (d & 7) >> 1;
            float2 e = up2(P2[a][kk]);
            if (d & 1) e.y = s0v * s0v; else e.x = s0v * s0v;
            P2[a][kk] = pk2(e.x, e.y);
        }
    }
    __syncthreads();

    const int s1 = cg & 1, s2 = (cg >> 1) & 1;

    for (int t = 1; t < TSEQ; ++t) {
        if (tid < 64) sh_y[tid] = obs[((size_t)t * BATCH + b) * 64 + tid];
        if (tid < 32) sh_u[tid] = ext[((size_t)(t - 1) * BATCH + b) * 32 + tid];
        __syncthreads();

        // ---- predict: mu += B u (into sh_mu) ; P += diag(q) ----
        if (tid < 64) {
            float s = sh_mu[tid];
            const float* Br = &sh_B[tid * 32];
            #pragma unroll 8
            for (int k = 0; k < 32; ++k) s += Br[k] * sh_u[k];
            sh_mu[tid] = s;
        }
        #pragma unroll
        for (int a = 0; a < 4; ++a) {
            int d = r0 + a;
            if ((d >> 3) == cg) {
                int kk = (d & 7) >> 1;
                float2 e = up2(P2[a][kk]);
                if (d & 1) e.y += sh_q[d]; else e.x += sh_q[d];
                P2[a][kk] = pk2(e.x, e.y);
            }
        }
        __syncthreads();

        // warp 0: mu col strip into registers (replicated across its 4 octets)
        u64 mc2[4];
        if (w0) {
            const ulonglong2* mp = (const ulonglong2*)&sh_mu[c0];
            ulonglong2 ma = mp[0], mb = mp[1];
            mc2[0] = ma.x; mc2[1] = ma.y; mc2[2] = mb.x; mc2[3] = mb.y;
        }

        // ---- 64 sequential scalar measurement updates ----
        #pragma unroll 1
        for (int i = 0; i < 64; ++i) {
            const int pb = i & 1;
            const ulonglong2* hp = (const ulonglong2*)&sh_H[(i << 6) + c0];
            ulonglong2 h01 = hp[0], h23 = hp[1];
            u64 h2[4] = {h01.x, h01.y, h23.x, h23.y};

            // vp[a] = partial of v[r0+a] over owned 8 cols (packed dots)
            float vp[4];
            #pragma unroll
            for (int a = 0; a < 4; ++a) {
                u64 acc = 0ull;
                ffma2(acc, P2[a][0], h2[0], acc);
                ffma2(acc, P2[a][1], h2[1], acc);
                ffma2(acc, P2[a][2], h2[2], acc);
                ffma2(acc, P2[a][3], h2[3], acc);
                float2 f = up2(acc);
                vp[a] = f.x + f.y;
            }
            // reduce-scatter over the 8-lane octet (4 shuffles)
            float ka = s1 ? vp[2] : vp[0];
            float kb = s1 ? vp[3] : vp[1];
            float sa = s1 ? vp[0] : vp[2];
            float sb = s1 ? vp[1] : vp[3];
            ka += __shfl_xor_sync(0xffffffffu, sa, 1);
            kb += __shfl_xor_sync(0xffffffffu, sb, 1);
            float kc = s2 ? kb : ka;
            float sc = s2 ? ka : kb;
            kc += __shfl_xor_sync(0xffffffffu, sc, 2);
            kc += __shfl_xor_sync(0xffffffffu, kc, 4);
            // lane cg holds v[r0 + 2*s1 + s2] (cg and cg^4 duplicate)
            if (cg < 4) sh_v[pb][r0 + 2 * s1 + s2] = kc;
            __syncthreads();

            // v col strip + own-row quad
            const ulonglong2* vpp = (const ulonglong2*)&sh_v[pb][c0];
            ulonglong2 va = vpp[0], vb = vpp[1];
            u64 vc2[4] = {va.x, va.y, vb.x, vb.y};
            float4 vr = *(const float4*)&sh_v[pb][r0];

            // s = h . v (octet-local full sum)
            u64 sacc = 0ull;
            ffma2(sacc, h2[0], vc2[0], sacc);
            ffma2(sacc, h2[1], vc2[1], sacc);
            ffma2(sacc, h2[2], vc2[2], sacc);
            ffma2(sacc, h2[3], vc2[3], sacc);
            float2 sf = up2(sacc);
            float sp = sf.x + sf.y;
            sp += __shfl_xor_sync(0xffffffffu, sp, 1);
            sp += __shfl_xor_sync(0xffffffffu, sp, 2);
            sp += __shfl_xor_sync(0xffffffffu, sp, 4);
            float rs = __fdividef(1.0f, sp + sh_r[i]);

            // warp 0: innovation + mu update (register mu)
            if (w0) {
                u64 wacc = 0ull;
                ffma2(wacc, h2[0], mc2[0], wacc);
                ffma2(wacc, h2[1], mc2[1], wacc);
                ffma2(wacc, h2[2], mc2[2], wacc);
                ffma2(wacc, h2[3], mc2[3], wacc);
                float2 wf = up2(wacc);
                float wp = wf.x + wf.y;
                wp += __shfl_xor_sync(0xffffffffu, wp, 1);
                wp += __shfl_xor_sync(0xffffffffu, wp, 2);
                wp += __shfl_xor_sync(0xffffffffu, wp, 4);
                float coef = (sh_y[i] - wp) * rs;
                u64 c2 = pk2(coef, coef);
                ffma2(mc2[0], c2, vc2[0], mc2[0]);
                ffma2(mc2[1], c2, vc2[1], mc2[1]);
                ffma2(mc2[2], c2, vc2[2], mc2[2]);
                ffma2(mc2[3], c2, vc2[3], mc2[3]);
            }

            // rank-1: P -= (v v^T) rs on owned tile (packed)
            {
                float w0f = -vr.x * rs, w1f = -vr.y * rs;
                float w2f = -vr.z * rs, w3f = -vr.w * rs;
                u64 wa = pk2(w0f, w0f), wb = pk2(w1f, w1f);
                u64 wc = pk2(w2f, w2f), wd = pk2(w3f, w3f);
                #pragma unroll
                for (int k = 0; k < 4; ++k) {
                    ffma2(P2[0][k], wa, vc2[k], P2[0][k]);
                    ffma2(P2[1][k], wb, vc2[k], P2[1][k]);
                    ffma2(P2[2][k], wc, vc2[k], P2[2][k]);
                    ffma2(P2[3][k], wd, vc2[k], P2[3][k]);
                }
            }
        }

        // ---- outputs ; publish mu for next predict ----
        if (tid < 8) {
            float2 m0 = up2(mc2[0]), m1 = up2(mc2[1]);
            float2 m2 = up2(mc2[2]), m3 = up2(mc2[3]);
            float4 lo = make_float4(m0.x, m0.y, m1.x, m1.y);
            float4 hi = make_float4(m2.x, m2.y, m3.x, m3.y);
            float* op = &outmu[((size_t)t * BATCH + b) * 64 + c0];
            *(float4*)op = lo;
            *(float4*)(op + 4) = hi;
            *(float4*)&sh_mu[c0] = lo;
            *(float4*)&sh_mu[c0 + 4] = hi;
        }
        #pragma unroll
        for (int a = 0; a < 4; ++a) {
            int d = r0 + a;
            if ((d >> 3) == cg) {
                float2 e = up2(P2[a][(d & 7) >> 1]);
                float dv = (d & 1) ? e.y : e.x;
                outls[((size_t)t * BATCH + b) * 64 + d] = 0.5f * logf(dv);
            }
        }
        __syncthreads();
    }
}

extern "C" void kernel_launch(void* const* d_in, const int* in_sizes, int n_in,
                              void* d_out, int out_size) {
    const float* ext  = (const float*)d_in[0];   // (500, 512, 32)
    const float* obs  = (const float*)d_in[1];   // (500, 512, 64)
    const float* mu0  = (const float*)d_in[2];   // (512, 64)
    const float* sg0  = (const float*)d_in[3];   // (512, 64)
    const float* lsig = (const float*)d_in[4];   // (64,)
    const float* Bm   = (const float*)d_in[5];   // (64, 32)
    const float* H    = (const float*)d_in[6];   // (64, 64)
    const float* ldel = (const float*)d_in[7];   // (64,)
    float* out = (float*)d_out;

    akf_main<<<BATCH, 128>>>(ext, obs, mu0, sg0, lsig, Bm, H, ldel, out);
}

// round 7
// speedup vs baseline: 3.4879x; 1.1362x over previous
#include <cuda_runtime.h>
#include <math.h>

#define TSEQ 500
#define BATCH 512

typedef unsigned long long u64;

__device__ __forceinline__ void ffma2(u64& d, u64 a, u64 b, u64 c) {
    asm("fma.rn.f32x2 %0, %1, %2, %3;" : "=l"(d) : "l"(a), "l"(b), "l"(c));
}
__device__ __forceinline__ float2 up2(u64 v) {
    float2 f; asm("mov.b64 {%0,%1}, %2;" : "=f"(f.x), "=f"(f.y) : "l"(v)); return f;
}
__device__ __forceinline__ u64 pk2(float x, float y) {
    u64 v; asm("mov.b64 %0, {%1,%2};" : "=l"(v) : "f"(x), "f"(y)); return v;
}

// phase-2 task table: rg -> (j, k); k==4 means "mu column" (innovation dot)
__constant__ int c_tj[16] = {0,1,1,2,2,2,3,3,3,3, 0,1,2,3, 0,0};
__constant__ int c_tk[16] = {0,0,1,0,1,2,0,1,2,3, 4,4,4,4, 0,0};

// 128 threads: rg = tid>>3 (16 row-groups x 4 rows), cg = tid&7 (8 col-groups x 8 cols).
// Thread (rg,cg) owns P[4rg..4rg+3][8cg..8cg+7] as 16 packed f32x2 registers.
// Measurement updates processed in blocks of K=4 with the exact identity
//   w_i = v_i - sum_{j<i} (u_j[i]/s_j) w_j,  u_i = G[:,i] - sum c_ji u_j,
// so only 2 barriers per 4 observations.

__global__ void __launch_bounds__(128, 4)
akf_main(const float* __restrict__ ext, const float* __restrict__ obs,
         const float* __restrict__ mu0, const float* __restrict__ sg0,
         const float* __restrict__ lsig, const float* __restrict__ Bm,
         const float* __restrict__ Hm, const float* __restrict__ ldel,
         float* __restrict__ out)
{
    __shared__ __align__(16) float sh_H[4096];
    __shared__ __align__(16) float sh_B[2048];
    __shared__ __align__(16) float sh_V[2][4][64];
    __shared__ __align__(16) float sh_mu[64];
    __shared__ float sh_G[16];   // G[j][k] (j>=k) at j*4+k
    __shared__ float sh_z[4];
    __shared__ float sh_y[64], sh_u[32], sh_r[64], sh_q[64];

    const int b   = blockIdx.x;
    const int tid = threadIdx.x;
    const int rg  = tid >> 3;
    const int cg  = tid & 7;
    const int r0  = rg << 2;
    const int c0  = cg << 3;
    const bool w0 = (tid < 32);
    const int s1 = cg & 1, s2 = (cg >> 1) & 1;

    for (int i = tid; i < 4096; i += 128) sh_H[i] = Hm[i];
    for (int i = tid; i < 2048; i += 128) sh_B[i] = Bm[i];
    if (tid < 64) {
        float e = expf(ldel[tid]); sh_r[tid] = e * e;
        float f = expf(lsig[tid]); sh_q[tid] = f * f;
    }

    u64 P2[4][4];
    #pragma unroll
    for (int a = 0; a < 4; ++a)
        #pragma unroll
        for (int k = 0; k < 4; ++k) P2[a][k] = 0ull;

    float* outmu = out;
    float* outls = out + (size_t)TSEQ * BATCH * 64;

    if (tid < 64) {
        float m0  = mu0[b * 64 + tid];
        float s0v = sg0[b * 64 + tid];
        sh_mu[tid] = m0;
        outmu[b * 64 + tid] = m0;
        outls[b * 64 + tid] = logf(s0v);
    }
    #pragma unroll
    for (int a = 0; a < 4; ++a) {
        int d = r0 + a;
        if ((d >> 3) == cg) {
            float s0v = sg0[b * 64 + d];
            int kk = (d & 7) >> 1;
            float2 e = up2(P2[a][kk]);
            if (d & 1) e.y = s0v * s0v; else e.x = s0v * s0v;
            P2[a][kk] = pk2(e.x, e.y);
        }
    }
    __syncthreads();

    for (int t = 1; t < TSEQ; ++t) {
        if (tid < 64) sh_y[tid] = obs[((size_t)t * BATCH + b) * 64 + tid];
        if (tid < 32) sh_u[tid] = ext[((size_t)(t - 1) * BATCH + b) * 32 + tid];
        __syncthreads();

        // ---- predict: mu += B u ; P += diag(q) ----
        if (tid < 64) {
            float s = sh_mu[tid];
            const float* Br = &sh_B[tid * 32];
            #pragma unroll 8
            for (int k = 0; k < 32; ++k) s += Br[k] * sh_u[k];
            sh_mu[tid] = s;
        }
        #pragma unroll
        for (int a = 0; a < 4; ++a) {
            int d = r0 + a;
            if ((d >> 3) == cg) {
                int kk = (d & 7) >> 1;
                float2 e = up2(P2[a][kk]);
                if (d & 1) e.y += sh_q[d]; else e.x += sh_q[d];
                P2[a][kk] = pk2(e.x, e.y);
            }
        }
        __syncthreads();

        // warp 0: mu strip into registers (replicated across its 4 octets)
        u64 mc2[4];
        if (w0) {
            const ulonglong2* mp = (const ulonglong2*)&sh_mu[c0];
            ulonglong2 ma = mp[0], mb = mp[1];
            mc2[0] = ma.x; mc2[1] = ma.y; mc2[2] = mb.x; mc2[3] = mb.y;
        }

        // ---- 16 blocks of 4 sequential scalar measurement updates ----
        #pragma unroll 1
        for (int blk = 0; blk < 16; ++blk) {
            const int o  = blk << 2;
            const int pb = blk & 1;
            float* V = &sh_V[pb][0][0];   // 4 rows of 64

            // publish current mu (warp0 rg==0 lanes own strips)
            if (tid < 8) {
                float2 m0f = up2(mc2[0]), m1f = up2(mc2[1]);
                float2 m2f = up2(mc2[2]), m3f = up2(mc2[3]);
                *(float4*)&sh_mu[c0]     = make_float4(m0f.x, m0f.y, m1f.x, m1f.y);
                *(float4*)&sh_mu[c0 + 4] = make_float4(m2f.x, m2f.y, m3f.x, m3f.y);
            }

            // ---- phase 1: V = P * H_blk^T (4 independent dot+scatter trees) ----
            #pragma unroll
            for (int j = 0; j < 4; ++j) {
                const ulonglong2* hp = (const ulonglong2*)&sh_H[((o + j) << 6) + c0];
                ulonglong2 ha = hp[0], hb = hp[1];
                u64 h2[4] = {ha.x, ha.y, hb.x, hb.y};
                float vp[4];
                #pragma unroll
                for (int a = 0; a < 4; ++a) {
                    u64 acc = 0ull;
                    ffma2(acc, P2[a][0], h2[0], acc);
                    ffma2(acc, P2[a][1], h2[1], acc);
                    ffma2(acc, P2[a][2], h2[2], acc);
                    ffma2(acc, P2[a][3], h2[3], acc);
                    float2 f = up2(acc);
                    vp[a] = f.x + f.y;
                }
                float ka = s1 ? vp[2] : vp[0];
                float kb = s1 ? vp[3] : vp[1];
                float sa = s1 ? vp[0] : vp[2];
                float sb = s1 ? vp[1] : vp[3];
                ka += __shfl_xor_sync(0xffffffffu, sa, 1);
                kb += __shfl_xor_sync(0xffffffffu, sb, 1);
                float kc = s2 ? kb : ka;
                float sc = s2 ? ka : kb;
                kc += __shfl_xor_sync(0xffffffffu, sc, 2);
                kc += __shfl_xor_sync(0xffffffffu, kc, 4);
                if (cg < 4) V[j * 64 + r0 + 2 * s1 + s2] = kc;
            }
            __syncthreads();   // B1

            // ---- phase 2: Gram entries + innovation dots (one task per rg) ----
            {
                int j = c_tj[rg], k = c_tk[rg];
                const ulonglong2* hp = (const ulonglong2*)&sh_H[((o + j) << 6) + c0];
                const float* vsrc = (k < 4) ? &V[k * 64] : sh_mu;
                const ulonglong2* vq = (const ulonglong2*)&vsrc[c0];
                ulonglong2 ha = hp[0], hb = hp[1];
                ulonglong2 va = vq[0], vb = vq[1];
                u64 acc = 0ull;
                ffma2(acc, ha.x, va.x, acc);
                ffma2(acc, ha.y, va.y, acc);
                ffma2(acc, hb.x, vb.x, acc);
                ffma2(acc, hb.y, vb.y, acc);
                float2 f = up2(acc);
                float g = f.x + f.y;
                g += __shfl_xor_sync(0xffffffffu, g, 1);
                g += __shfl_xor_sync(0xffffffffu, g, 2);
                g += __shfl_xor_sync(0xffffffffu, g, 4);
                if (cg == 0 && rg < 14) {
                    if (k < 4) sh_G[j * 4 + k] = g;
                    else       sh_z[j] = g;
                }
            }
            __syncthreads();   // B2

            // ---- phase 3: redundant K-space recursion (exact) ----
            float u01 = sh_G[4],  u02 = sh_G[8],  u03 = sh_G[12];
            float rs0 = __fdividef(1.0f, sh_G[0] + sh_r[o + 0]);
            float c01 = u01 * rs0, c02 = u02 * rs0, c03 = u03 * rs0;
            float u12 = sh_G[9]  - c01 * u02;
            float u13 = sh_G[13] - c01 * u03;
            float rs1 = __fdividef(1.0f, (sh_G[5] - c01 * u01) + sh_r[o + 1]);
            float c12 = u12 * rs1, c13 = u13 * rs1;
            float u23 = sh_G[14] - c02 * u03 - c12 * u13;
            float rs2 = __fdividef(1.0f, (sh_G[10] - c02 * u02 - c12 * u12) + sh_r[o + 2]);
            float c23 = u23 * rs2;
            float rs3 = __fdividef(1.0f, (sh_G[15] - c03 * u03 - c13 * u13 - c23 * u23) + sh_r[o + 3]);
            float f0 = (sh_y[o + 0] - sh_z[0]) * rs0;
            float f1 = (sh_y[o + 1] - sh_z[1] - u01 * f0) * rs1;
            float f2 = (sh_y[o + 2] - sh_z[2] - u02 * f0 - u12 * f1) * rs2;
            float f3 = (sh_y[o + 3] - sh_z[3] - u03 * f0 - u13 * f1 - u23 * f2) * rs3;

            // ---- phase 4: w strips (in-register), rank-4 update, mu update ----
            u64 wc[4][4];
            {
                const ulonglong2* q0 = (const ulonglong2*)&V[0 * 64 + c0];
                const ulonglong2* q1 = (const ulonglong2*)&V[1 * 64 + c0];
                const ulonglong2* q2 = (const ulonglong2*)&V[2 * 64 + c0];
                const ulonglong2* q3 = (const ulonglong2*)&V[3 * 64 + c0];
                ulonglong2 a0 = q0[0], b0 = q0[1];
                wc[0][0] = a0.x; wc[0][1] = a0.y; wc[0][2] = b0.x; wc[0][3] = b0.y;
                ulonglong2 a1 = q1[0], b1 = q1[1];
                wc[1][0] = a1.x; wc[1][1] = a1.y; wc[1][2] = b1.x; wc[1][3] = b1.y;
                ulonglong2 a2 = q2[0], b2 = q2[1];
                wc[2][0] = a2.x; wc[2][1] = a2.y; wc[2][2] = b2.x; wc[2][3] = b2.y;
                ulonglong2 a3 = q3[0], b3 = q3[1];
                wc[3][0] = a3.x; wc[3][1] = a3.y; wc[3][2] = b3.x; wc[3][3] = b3.y;
                u64 n01 = pk2(-c01, -c01), n02 = pk2(-c02, -c02), n03 = pk2(-c03, -c03);
                u64 n12 = pk2(-c12, -c12), n13 = pk2(-c13, -c13), n23 = pk2(-c23, -c23);
                #pragma unroll
                for (int k = 0; k < 4; ++k) {
                    ffma2(wc[1][k], n01, wc[0][k], wc[1][k]);
                    ffma2(wc[2][k], n02, wc[0][k], wc[2][k]);
                    ffma2(wc[2][k], n12, wc[1][k], wc[2][k]);
                    ffma2(wc[3][k], n03, wc[0][k], wc[3][k]);
                    ffma2(wc[3][k], n13, wc[1][k], wc[3][k]);
                    ffma2(wc[3][k], n23, wc[2][k], wc[3][k]);
                }
            }
            // w row quads
            float4 w0r = *(const float4*)&V[0 * 64 + r0];
            float4 w1r = *(const float4*)&V[1 * 64 + r0];
            float4 w2r = *(const float4*)&V[2 * 64 + r0];
            float4 w3r = *(const float4*)&V[3 * 64 + r0];
            w1r.x -= c01 * w0r.x; w1r.y -= c01 * w0r.y; w1r.z -= c01 * w0r.z; w1r.w -= c01 * w0r.w;
            w2r.x -= c02 * w0r.x + c12 * w1r.x; w2r.y -= c02 * w0r.y + c12 * w1r.y;
            w2r.z -= c02 * w0r.z + c12 * w1r.z; w2r.w -= c02 * w0r.w + c12 * w1r.w;
            w3r.x -= c03 * w0r.x + c13 * w1r.x + c23 * w2r.x;
            w3r.y -= c03 * w0r.y + c13 * w1r.y + c23 * w2r.y;
            w3r.z -= c03 * w0r.z + c13 * w1r.z + c23 * w2r.z;
            w3r.w -= c03 * w0r.w + c13 * w1r.w + c23 * w2r.w;

            // rank-4: P -= sum_i rs_i * w_i w_i^T  (owned tile)
            #pragma unroll
            for (int i = 0; i < 4; ++i) {
                float4 wr = (i == 0) ? w0r : (i == 1) ? w1r : (i == 2) ? w2r : w3r;
                float rsv = (i == 0) ? rs0 : (i == 1) ? rs1 : (i == 2) ? rs2 : rs3;
                float g0 = -wr.x * rsv, g1 = -wr.y * rsv, g2 = -wr.z * rsv, g3 = -wr.w * rsv;
                u64 ga = pk2(g0, g0), gb = pk2(g1, g1), gc = pk2(g2, g2), gd = pk2(g3, g3);
                #pragma unroll
                for (int k = 0; k < 4; ++k) {
                    ffma2(P2[0][k], ga, wc[i][k], P2[0][k]);
                    ffma2(P2[1][k], gb, wc[i][k], P2[1][k]);
                    ffma2(P2[2][k], gc, wc[i][k], P2[2][k]);
                    ffma2(P2[3][k], gd, wc[i][k], P2[3][k]);
                }
            }
            // mu += sum_i f_i * w_i  (warp 0, register strips)
            if (w0) {
                u64 f02 = pk2(f0, f0), f12 = pk2(f1, f1);
                u64 f22 = pk2(f2, f2), f32 = pk2(f3, f3);
                #pragma unroll
                for (int k = 0; k < 4; ++k) {
                    ffma2(mc2[k], f02, wc[0][k], mc2[k]);
                    ffma2(mc2[k], f12, wc[1][k], mc2[k]);
                    ffma2(mc2[k], f22, wc[2][k], mc2[k]);
                    ffma2(mc2[k], f32, wc[3][k], mc2[k]);
                }
            }
        }

        // ---- outputs ; publish mu for next predict ----
        if (tid < 8) {
            float2 m0f = up2(mc2[0]), m1f = up2(mc2[1]);
            float2 m2f = up2(mc2[2]), m3f = up2(mc2[3]);
            float4 lo = make_float4(m0f.x, m0f.y, m1f.x, m1f.y);
            float4 hi = make_float4(m2f.x, m2f.y, m3f.x, m3f.y);
            float* op = &outmu[((size_t)t * BATCH + b) * 64 + c0];
            *(float4*)op = lo;
            *(float4*)(op + 4) = hi;
            *(float4*)&sh_mu[c0] = lo;
            *(float4*)&sh_mu[c0 + 4] = hi;
        }
        #pragma unroll
        for (int a = 0; a < 4; ++a) {
            int d = r0 + a;
            if ((d >> 3) == cg) {
                float2 e = up2(P2[a][(d & 7) >> 1]);
                float dv = (d & 1) ? e.y : e.x;
                outls[((size_t)t * BATCH + b) * 64 + d] = 0.5f * logf(dv);
            }
        }
        __syncthreads();
    }
}

extern "C" void kernel_launch(void* const* d_in, const int* in_sizes, int n_in,
                              void* d_out, int out_size) {
    const float* ext  = (const float*)d_in[0];   // (500, 512, 32)
    const float* obs  = (const float*)d_in[1];   // (500, 512, 64)
    const float* mu0  = (const float*)d_in[2];   // (512, 64)
    const float* sg0  = (const float*)d_in[3];   // (512, 64)
    const float* lsig = (const float*)d_in[4];   // (64,)
    const float* Bm   = (const float*)d_in[5];   // (64, 32)
    const float* H    = (const float*)d_in[6];   // (64, 64)
    const float* ldel = (const float*)d_in[7];   // (64,)
    float* out = (float*)d_out;

    akf_main<<<BATCH, 128>>>(ext, obs, mu0, sg0, lsig, Bm, H, ldel, out);
}